// round 1
// baseline (speedup 1.0000x reference)
#include <cuda_runtime.h>
#include <stdint.h>

#define BATCH 32
#define NPTS  8192
#define NCLST 64
#define C1    128
#define C2    256
#define CF    512
#define CO    384
#define PTOT  (BATCH*NPTS)
#define ENC_NEG_INF 0x007FFFFFu

// ---- scratch (static device globals; no runtime allocation) ----
__device__ float    g_feat[(size_t)PTOT * C2];        // 256 MB feat scratch
__device__ unsigned g_fg[BATCH*NCLST*C2];             // encoded cluster max of feat
__device__ unsigned g_om[BATCH*NCLST*CO];             // encoded cluster max of out

// monotonic order-preserving float<->uint encoding (for atomicMax on floats)
__device__ __forceinline__ unsigned enc(float f){
  unsigned u = __float_as_uint(f);
  return (u & 0x80000000u) ? ~u : (u | 0x80000000u);
}
__device__ __forceinline__ float dec(unsigned u){
  u = (u & 0x80000000u) ? (u & 0x7FFFFFFFu) : ~u;
  return __uint_as_float(u);
}

__global__ void k_init(){
  int i = blockIdx.x*blockDim.x + threadIdx.x;
  if (i < BATCH*NCLST*C2) g_fg[i] = ENC_NEG_INF;
  if (i < BATCH*NCLST*CO) g_om[i] = ENC_NEG_INF;
}

// =====================================================================
// Stage 1: h = relu(bn1(xyz @ w1^T + b1));  feat = h @ w2^T + b2
//          write feat scratch + atomicMax into g_fg
// CTA: 256 threads, 64 points
// =====================================================================
#define TM1 64
__global__ __launch_bounds__(256, 2) void k_stage1(
    const float* __restrict__ xyz, const int* __restrict__ choice,
    const float* __restrict__ w1,  const float* __restrict__ b1,
    const float* __restrict__ bg1, const float* __restrict__ bb1,
    const float* __restrict__ bm1, const float* __restrict__ bv1,
    const float* __restrict__ w2,  const float* __restrict__ b2)
{
  extern __shared__ float sm[];
  float* sh = sm;              // h tile [64][128]
  float* sw = sm + TM1*C1;     // w2 stage [16][C2+1]
  __shared__ float sx[TM1][3];
  __shared__ int   scl[TM1];

  const int t  = threadIdx.x;
  const int p0 = blockIdx.x * TM1;

  for (int i=t; i<TM1*3; i+=256) sx[i/3][i%3] = xyz[(size_t)p0*3 + i];
  for (int i=t; i<TM1;   i+=256) scl[i] = choice[p0+i];
  __syncthreads();

  // h = relu(bn1(xyz @ w1^T + b1)), BN folded into (s, t)
  for (int i=t; i<TM1*C1; i+=256){
    int pt = i >> 7, ch = i & (C1-1);
    float s  = bg1[ch] * rsqrtf(bv1[ch] + 1e-5f);
    float tt = bb1[ch] - bm1[ch]*s;
    float a  = fmaf(sx[pt][0], w1[ch*3+0],
               fmaf(sx[pt][1], w1[ch*3+1],
               fmaf(sx[pt][2], w1[ch*3+2], b1[ch])));
    sh[pt*C1+ch] = fmaxf(fmaf(a, s, tt), 0.f);
  }
  __syncthreads();

  // feat GEMM: 64 pts x 256 ch, k = 128. Thread = 4 pts x 16 ch.
  const int ptg = t >> 4;     // 0..15
  const int chg = t & 15;     // ch = chg + 16*j

  float acc[4][16];
  #pragma unroll
  for (int i=0;i<4;i++)
    #pragma unroll
    for (int j=0;j<16;j++) acc[i][j] = 0.f;

  for (int k0=0; k0<C1; k0+=16){
    // stage w2[ch][k0..k0+15] into sw[kk*(C2+1)+ch] (coalesced global, cf-free smem)
    for (int i=t; i<C2*16; i+=256){
      int kk = i & 15, ch = i >> 4;
      sw[kk*(C2+1) + ch] = w2[ch*C1 + k0 + kk];
    }
    __syncthreads();
    #pragma unroll
    for (int kk=0; kk<16; kk++){
      float fv[4];
      #pragma unroll
      for (int i=0;i<4;i++) fv[i] = sh[(ptg*4+i)*C1 + k0 + kk];
      const float* wr = &sw[kk*(C2+1) + chg];
      #pragma unroll
      for (int j=0;j<16;j++){
        float w = wr[16*j];
        #pragma unroll
        for (int i=0;i<4;i++) acc[i][j] = fmaf(fv[i], w, acc[i][j]);
      }
    }
    __syncthreads();
  }

  #pragma unroll
  for (int i=0;i<4;i++){
    int pt = ptg*4 + i;
    int pg = p0 + pt;
    int b  = pg >> 13;                    // /8192
    unsigned* fgr = &g_fg[(size_t)(b*NCLST + scl[pt])*C2];
    float*    fr  = &g_feat[(size_t)pg * C2];
    #pragma unroll
    for (int j=0;j<16;j++){
      int ch = chg + 16*j;
      float v = acc[i][j] + b2[ch];
      fr[ch] = v;
      atomicMax(&fgr[ch], enc(v));
    }
  }
}

// =====================================================================
// Stage 2: f = [fg[choice] , feat]  (512)
//          h2 = relu(bn2(f @ w3^T + b3))
//          out = h2 @ w4^T + b4  -> atomicMax into g_om
// CTA: 256 threads, 32 points, ~96KB smem, 2 CTAs/SM
// =====================================================================
#define TM2 32
__global__ __launch_bounds__(256, 2) void k_stage2(
    const int*   __restrict__ choice,
    const float* __restrict__ w3,  const float* __restrict__ b3,
    const float* __restrict__ bg2, const float* __restrict__ bb2,
    const float* __restrict__ bm2, const float* __restrict__ bv2,
    const float* __restrict__ w4,  const float* __restrict__ b4)
{
  extern __shared__ float sm[];
  float* sf = sm;              // f tile [32][512], reused as h2 tile
  float* sw = sm + TM2*CF;     // weight stage [16][CF+1]
  __shared__ int scl[TM2];

  const int t  = threadIdx.x;
  const int p0 = blockIdx.x * TM2;
  const int b  = p0 >> 13;

  for (int i=t; i<TM2; i+=256) scl[i] = choice[p0+i];
  __syncthreads();

  // build f tile: [0:256) = decoded cluster max, [256:512) = feat
  for (int i=t; i<TM2*CF; i+=256){
    int pt = i >> 9, c = i & (CF-1);
    float v;
    if (c < C2) v = dec(g_fg[(size_t)(b*NCLST + scl[pt])*C2 + c]);
    else        v = g_feat[(size_t)(p0+pt)*C2 + (c - C2)];
    sf[i] = v;
  }
  __syncthreads();

  const int ptg = t >> 5;     // 0..7, warp-uniform -> broadcast f reads
  const int chg = t & 31;     // ch = chg + 32*j

  float acc[4][16];
  #pragma unroll
  for (int i=0;i<4;i++)
    #pragma unroll
    for (int j=0;j<16;j++) acc[i][j] = 0.f;

  // ---- GEMM2: h2 = f @ w3^T, k = 512 ----
  for (int k0=0; k0<CF; k0+=16){
    for (int i=t; i<CF*16; i+=256){
      int kk = i & 15, ch = i >> 4;
      sw[kk*(CF+1) + ch] = w3[ch*CF + k0 + kk];
    }
    __syncthreads();
    #pragma unroll
    for (int kk=0; kk<16; kk++){
      float fv[4];
      #pragma unroll
      for (int i=0;i<4;i++) fv[i] = sf[(ptg*4+i)*CF + k0 + kk];
      const float* wr = &sw[kk*(CF+1) + chg];
      #pragma unroll
      for (int j=0;j<16;j++){
        float w = wr[32*j];
        #pragma unroll
        for (int i=0;i<4;i++) acc[i][j] = fmaf(fv[i], w, acc[i][j]);
      }
    }
    __syncthreads();
  }

  // bn2 + relu epilogue in place (all sf reads complete after trailing sync)
  #pragma unroll
  for (int j=0;j<16;j++){
    int ch = chg + 32*j;
    float s  = bg2[ch] * rsqrtf(bv2[ch] + 1e-5f);
    float tt = bb2[ch] - bm2[ch]*s;
    float bb = b3[ch];
    #pragma unroll
    for (int i=0;i<4;i++)
      acc[i][j] = fmaxf(fmaf(acc[i][j] + bb, s, tt), 0.f);
  }
  // write h2 back over sf
  #pragma unroll
  for (int j=0;j<16;j++){
    int ch = chg + 32*j;
    #pragma unroll
    for (int i=0;i<4;i++)
      sf[(ptg*4+i)*CF + ch] = acc[i][j];
  }
  __syncthreads();

  // ---- GEMM3: out = h2 @ w4^T, 384 ch, k = 512 ----
  #pragma unroll
  for (int i=0;i<4;i++)
    #pragma unroll
    for (int j=0;j<12;j++) acc[i][j] = 0.f;

  for (int k0=0; k0<CF; k0+=16){
    for (int i=t; i<CO*16; i+=256){
      int kk = i & 15, ch = i >> 4;
      sw[kk*(CF+1) + ch] = w4[ch*CF + k0 + kk];
    }
    __syncthreads();
    #pragma unroll
    for (int kk=0; kk<16; kk++){
      float fv[4];
      #pragma unroll
      for (int i=0;i<4;i++) fv[i] = sf[(ptg*4+i)*CF + k0 + kk];
      const float* wr = &sw[kk*(CF+1) + chg];
      #pragma unroll
      for (int j=0;j<12;j++){
        float w = wr[32*j];
        #pragma unroll
        for (int i=0;i<4;i++) acc[i][j] = fmaf(fv[i], w, acc[i][j]);
      }
    }
    __syncthreads();
  }

  #pragma unroll
  for (int i=0;i<4;i++){
    int pt = ptg*4 + i;
    unsigned* orow = &g_om[(size_t)(b*NCLST + scl[pt])*CO];
    #pragma unroll
    for (int j=0;j<12;j++){
      int ch = chg + 32*j;
      atomicMax(&orow[ch], enc(acc[i][j] + b4[ch]));
    }
  }
}

__global__ void k_final(float* __restrict__ out){
  int i = blockIdx.x*blockDim.x + threadIdx.x;
  if (i < BATCH*NCLST*CO) out[i] = dec(g_om[i]);
}

// =====================================================================
extern "C" void kernel_launch(void* const* d_in, const int* in_sizes, int n_in,
                              void* d_out, int out_size)
{
  const float* xyz    = (const float*)d_in[0];
  const int*   choice = (const int*)  d_in[1];
  const float* w1  = (const float*)d_in[2];
  const float* b1  = (const float*)d_in[3];
  const float* g1  = (const float*)d_in[4];
  const float* bb1 = (const float*)d_in[5];
  const float* m1  = (const float*)d_in[6];
  const float* v1  = (const float*)d_in[7];
  const float* w2  = (const float*)d_in[8];
  const float* b2  = (const float*)d_in[9];
  const float* w3  = (const float*)d_in[10];
  const float* b3  = (const float*)d_in[11];
  const float* g2  = (const float*)d_in[12];
  const float* bb2 = (const float*)d_in[13];
  const float* m2  = (const float*)d_in[14];
  const float* v2  = (const float*)d_in[15];
  const float* w4  = (const float*)d_in[16];
  const float* b4  = (const float*)d_in[17];

  size_t smem1 = (size_t)(TM1*C1 + 16*(C2+1)) * sizeof(float);   // ~48.1 KB
  size_t smem2 = (size_t)(TM2*CF + 16*(CF+1)) * sizeof(float);   // ~96.1 KB
  cudaFuncSetAttribute(k_stage1, cudaFuncAttributeMaxDynamicSharedMemorySize, (int)smem1);
  cudaFuncSetAttribute(k_stage2, cudaFuncAttributeMaxDynamicSharedMemorySize, (int)smem2);

  int ntot = BATCH*NCLST*CO;
  k_init  <<<(ntot+255)/256, 256>>>();
  k_stage1<<<PTOT/TM1, 256, smem1>>>(xyz, choice, w1,b1,g1,bb1,m1,v1,w2,b2);
  k_stage2<<<PTOT/TM2, 256, smem2>>>(choice, w3,b3,g2,bb2,m2,v2,w4,b4);
  k_final <<<(ntot+255)/256, 256>>>((float*)d_out);
}

// round 3
// speedup vs baseline: 4.0851x; 4.0851x over previous
#include <cuda_runtime.h>
#include <cuda_bf16.h>
#include <stdint.h>

#define BATCH 32
#define NPTS  8192
#define NCLST 64
#define C1    128
#define C2    256
#define CF    512
#define CO    384
#define PTOT  (BATCH*NPTS)
#define ENC_NEG_INF 0x007FFFFFu

// ---------------- scratch (static device globals) ----------------
__device__ unsigned g_fg[BATCH*NCLST*C2];            // encoded cluster max of feat
__device__ unsigned g_om[BATCH*NCLST*CO];            // encoded cluster max of out
__device__ uint32_t g_featp[(size_t)PTOT*C2];        // feat split-bf16 packed (hi|lo<<16)
__device__ uint32_t g_fgp[BATCH*NCLST*C2];           // fg split packed
__device__ uint32_t g_h2p[(size_t)PTOT*CF];          // h2 split packed
__device__ uint32_t g_w3p[CF*CF];                    // w3 split packed
__device__ uint32_t g_w4p[CO*CF];                    // w4 split packed
__device__ float    g_s2[CF], g_t2[CF];              // folded BN2 scale/shift (incl b3)

// ---------------- helpers ----------------
__device__ __forceinline__ unsigned enc(float f){
  unsigned u = __float_as_uint(f);
  return (u & 0x80000000u) ? ~u : (u | 0x80000000u);
}
__device__ __forceinline__ float dec(unsigned u){
  u = (u & 0x80000000u) ? (u & 0x7FFFFFFFu) : ~u;
  return __uint_as_float(u);
}
__device__ __forceinline__ uint32_t pack_split(float v){
  __nv_bfloat16 bh = __float2bfloat16(v);
  float r = v - __bfloat162float(bh);
  if (!(r == r)) r = 0.f;
  __nv_bfloat16 bl = __float2bfloat16(r);
  return (uint32_t)__bfloat16_as_ushort(bh) | ((uint32_t)__bfloat16_as_ushort(bl) << 16);
}
__device__ __forceinline__ uint32_t smem_u32(const void* p){
  uint32_t a;
  asm("{ .reg .u64 t; cvta.to.shared.u64 t, %1; cvt.u32.u64 %0, t; }" : "=r"(a) : "l"(p));
  return a;
}

// baseline-PTX tensor ops (compute_103-safe): ldmatrix + mma.sync bf16
__device__ __forceinline__ void ldsm4(uint32_t* r, uint32_t addr){
  asm volatile("ldmatrix.sync.aligned.m8n8.x4.shared.b16 {%0,%1,%2,%3}, [%4];"
    : "=r"(r[0]),"=r"(r[1]),"=r"(r[2]),"=r"(r[3]) : "r"(addr));
}
__device__ __forceinline__ void mma16816(float* c, const uint32_t* a, const uint32_t* b){
  asm volatile("mma.sync.aligned.m16n8k16.row.col.f32.bf16.bf16.f32 "
    "{%0,%1,%2,%3}, {%4,%5,%6,%7}, {%8,%9}, {%0,%1,%2,%3};"
    : "+f"(c[0]),"+f"(c[1]),"+f"(c[2]),"+f"(c[3])
    : "r"(a[0]),"r"(a[1]),"r"(a[2]),"r"(a[3]), "r"(b[0]),"r"(b[1]));
}

// smem plane geometry: rows padded to 80B (32 bf16 + 8 pad) -> cf-free ldmatrix
#define ROWB   80
#define PLANE  (128*ROWB)   // 10240 B
#define KC     32

// =====================================================================
__global__ void k_init(){
  int i = blockIdx.x*blockDim.x + threadIdx.x;
  if (i < BATCH*NCLST*C2) g_fg[i] = ENC_NEG_INF;
  if (i < BATCH*NCLST*CO) g_om[i] = ENC_NEG_INF;
}

__global__ void k_prep(const float* __restrict__ w3, const float* __restrict__ w4,
                       const float* __restrict__ b3,
                       const float* __restrict__ bg2, const float* __restrict__ bb2,
                       const float* __restrict__ bm2, const float* __restrict__ bv2){
  int i = blockIdx.x*blockDim.x + threadIdx.x;
  if (i < CF*CF) g_w3p[i] = pack_split(w3[i]);
  int j = i - CF*CF;
  if (j >= 0 && j < CO*CF) g_w4p[j] = pack_split(w4[j]);
  int k = i - CF*CF - CO*CF;
  if (k >= 0 && k < CF){
    float s = bg2[k] * rsqrtf(bv2[k] + 1e-5f);
    g_s2[k] = s;
    g_t2[k] = bb2[k] + (b3[k] - bm2[k]) * s;
  }
}

// =====================================================================
// Stage 1 (fp32): feat = (relu(bn1(xyz@w1^T+b1)))@w2^T + b2
// =====================================================================
#define TM1 64
__global__ __launch_bounds__(256, 2) void k_stage1(
    const float* __restrict__ xyz, const int* __restrict__ choice,
    const float* __restrict__ w1,  const float* __restrict__ b1,
    const float* __restrict__ bg1, const float* __restrict__ bb1,
    const float* __restrict__ bm1, const float* __restrict__ bv1,
    const float* __restrict__ w2,  const float* __restrict__ b2)
{
  extern __shared__ float sm[];
  float* sh = sm;
  float* sw = sm + TM1*C1;
  __shared__ float sx[TM1][3];
  __shared__ int   scl[TM1];

  const int t  = threadIdx.x;
  const int p0 = blockIdx.x * TM1;

  for (int i=t; i<TM1*3; i+=256) sx[i/3][i%3] = xyz[(size_t)p0*3 + i];
  for (int i=t; i<TM1;   i+=256) scl[i] = choice[p0+i];
  __syncthreads();

  for (int i=t; i<TM1*C1; i+=256){
    int pt = i >> 7, ch = i & (C1-1);
    float s  = bg1[ch] * rsqrtf(bv1[ch] + 1e-5f);
    float tt = bb1[ch] - bm1[ch]*s;
    float a  = fmaf(sx[pt][0], w1[ch*3+0],
               fmaf(sx[pt][1], w1[ch*3+1],
               fmaf(sx[pt][2], w1[ch*3+2], b1[ch])));
    sh[pt*C1+ch] = fmaxf(fmaf(a, s, tt), 0.f);
  }
  __syncthreads();

  const int ptg = t >> 4;
  const int chg = t & 15;

  float acc[4][16];
  #pragma unroll
  for (int i=0;i<4;i++)
    #pragma unroll
    for (int j=0;j<16;j++) acc[i][j] = 0.f;

  for (int k0=0; k0<C1; k0+=16){
    for (int i=t; i<C2*16; i+=256){
      int kk = i & 15, ch = i >> 4;
      sw[kk*(C2+1) + ch] = w2[ch*C1 + k0 + kk];
    }
    __syncthreads();
    #pragma unroll
    for (int kk=0; kk<16; kk++){
      float fv[4];
      #pragma unroll
      for (int i=0;i<4;i++) fv[i] = sh[(ptg*4+i)*C1 + k0 + kk];
      const float* wr = &sw[kk*(C2+1) + chg];
      #pragma unroll
      for (int j=0;j<16;j++){
        float w = wr[16*j];
        #pragma unroll
        for (int i=0;i<4;i++) acc[i][j] = fmaf(fv[i], w, acc[i][j]);
      }
    }
    __syncthreads();
  }

  #pragma unroll
  for (int i=0;i<4;i++){
    int pt = ptg*4 + i;
    int pg = p0 + pt;
    int b  = pg >> 13;
    unsigned* fgr = &g_fg[(size_t)(b*NCLST + scl[pt])*C2];
    uint32_t* fr  = &g_featp[(size_t)pg * C2];
    #pragma unroll
    for (int j=0;j<16;j++){
      int ch = chg + 16*j;
      float v = acc[i][j] + b2[ch];
      fr[ch] = pack_split(v);
      atomicMax(&fgr[ch], enc(v));
    }
  }
}

__global__ void k_fg_split(){
  int i = blockIdx.x*blockDim.x + threadIdx.x;
  if (i < BATCH*NCLST*C2) g_fgp[i] = pack_split(dec(g_fg[i]));
}

// =====================================================================
// HMMA GEMM core: C[128 pts][128 ch] tile, k staged in 32-chunks,
// split-bf16 3-term. 8 warps: warp = 64 rows x 32 cols.
// =====================================================================
struct Frag { float acc[4][4][4]; };  // [mi][ni][c0..c3]

template<bool GATHER_A>  // gemm2 gathers f = [fg|feat]; gemm3 reads h2p linear
__device__ __forceinline__ void gemm_core(
    char* smem, const int* scl, int p0, int bb, int ch0,
    const uint32_t* __restrict__ Bsrc, int KTOT, Frag& F)
{
  const int t = threadIdx.x, lane = t & 31, wid = t >> 5;
  const int wm = (wid & 1) * 64;
  const int wn = (wid >> 1) * 32;

  char* pAh = smem;
  char* pAl = smem + PLANE;
  char* pBh = smem + 2*PLANE;
  char* pBl = smem + 3*PLANE;
  const uint32_t aAh = smem_u32(pAh), aAl = smem_u32(pAl);
  const uint32_t aBh = smem_u32(pBh), aBl = smem_u32(pBl);

  // per-lane ldmatrix offsets
  const uint32_t aoff = (uint32_t)(wm + (lane & 15)) * ROWB + ((lane >> 4) & 1) * 16;
  const uint32_t boff = (uint32_t)(wn + (lane & 7) + ((lane >> 4) & 1) * 8) * ROWB
                      + ((lane >> 3) & 1) * 16;

  #pragma unroll
  for (int mi=0;mi<4;mi++)
    #pragma unroll
    for (int ni=0;ni<4;ni++)
      #pragma unroll
      for (int c=0;c<4;c++) F.acc[mi][ni][c] = 0.f;

  const int NKC = KTOT / KC;
  for (int kc = 0; kc < NKC; kc++){
    // ---- stage A (128 rows x 32 k, hi/lo planes) ----
    for (int idx = t; idx < 2048; idx += 256){
      int row = idx >> 4, kp = idx & 15;
      size_t off;
      const uint32_t* src;
      if (GATHER_A){
        if (kc < 8){ off = ((size_t)(bb*NCLST + scl[row]))*C2 + kc*KC + kp*2; src = g_fgp; }
        else       { off = ((size_t)(p0 + row))*C2 + (kc-8)*KC + kp*2;        src = g_featp; }
      } else {
        off = ((size_t)(p0 + row))*CF + kc*KC + kp*2; src = g_h2p;
      }
      uint2 v = *(const uint2*)(src + off);
      uint32_t so = (uint32_t)row*ROWB + kp*4;
      *(uint32_t*)(pAh + so) = __byte_perm(v.x, v.y, 0x5410);
      *(uint32_t*)(pAl + so) = __byte_perm(v.x, v.y, 0x7632);
    }
    // ---- stage B (128 ch rows x 32 k) ----
    for (int idx = t; idx < 2048; idx += 256){
      int row = idx >> 4, kp = idx & 15;
      uint2 v = *(const uint2*)(Bsrc + ((size_t)(ch0 + row))*CF + kc*KC + kp*2);
      uint32_t so = (uint32_t)row*ROWB + kp*4;
      *(uint32_t*)(pBh + so) = __byte_perm(v.x, v.y, 0x5410);
      *(uint32_t*)(pBl + so) = __byte_perm(v.x, v.y, 0x7632);
    }
    __syncthreads();

    #pragma unroll
    for (int ks = 0; ks < 2; ks++){
      const uint32_t kb = ks * 32;
      uint32_t a[4][4], bH[2][4], bL[2][4];
      #pragma unroll
      for (int mi=0;mi<4;mi++) ldsm4(a[mi],  aAh + aoff + mi*(16*ROWB) + kb);
      #pragma unroll
      for (int nj=0;nj<2;nj++) ldsm4(bH[nj], aBh + boff + nj*(16*ROWB) + kb);
      // term 1: A_hi * B_hi
      #pragma unroll
      for (int mi=0;mi<4;mi++)
        #pragma unroll
        for (int nj=0;nj<2;nj++){
          mma16816(F.acc[mi][nj*2+0], a[mi], &bH[nj][0]);
          mma16816(F.acc[mi][nj*2+1], a[mi], &bH[nj][2]);
        }
      // term 2: A_hi * B_lo
      #pragma unroll
      for (int nj=0;nj<2;nj++) ldsm4(bL[nj], aBl + boff + nj*(16*ROWB) + kb);
      #pragma unroll
      for (int mi=0;mi<4;mi++)
        #pragma unroll
        for (int nj=0;nj<2;nj++){
          mma16816(F.acc[mi][nj*2+0], a[mi], &bL[nj][0]);
          mma16816(F.acc[mi][nj*2+1], a[mi], &bL[nj][2]);
        }
      // term 3: A_lo * B_hi (reuse a regs)
      #pragma unroll
      for (int mi=0;mi<4;mi++) ldsm4(a[mi], aAl + aoff + mi*(16*ROWB) + kb);
      #pragma unroll
      for (int mi=0;mi<4;mi++)
        #pragma unroll
        for (int nj=0;nj<2;nj++){
          mma16816(F.acc[mi][nj*2+0], a[mi], &bH[nj][0]);
          mma16816(F.acc[mi][nj*2+1], a[mi], &bH[nj][2]);
        }
    }
    __syncthreads();
  }
}

// GEMM2: h2 = relu(bn2(f @ w3^T + b3)) -> split-packed scratch
__global__ __launch_bounds__(256) void k_gemm2(const int* __restrict__ choice)
{
  extern __shared__ char smem[];
  __shared__ int scl[128];
  const int t = threadIdx.x, lane = t & 31, wid = t >> 5;
  const int p0 = blockIdx.x * 128, bb = blockIdx.x >> 6;
  const int ch0 = blockIdx.y * 128;

  for (int i=t; i<128; i+=256) scl[i] = choice[p0+i];
  __syncthreads();

  Frag F;
  gemm_core<true>(smem, scl, p0, bb, ch0, g_w3p, CF, F);

  const int wm = (wid & 1) * 64, wn = (wid >> 1) * 32;
  const int r0 = lane >> 2, cp = (lane & 3) * 2;
  #pragma unroll
  for (int mi=0;mi<4;mi++){
    #pragma unroll
    for (int ni=0;ni<4;ni++){
      int ch = ch0 + wn + ni*8 + cp;
      float s0 = g_s2[ch], s1 = g_s2[ch+1];
      float t0 = g_t2[ch], t1 = g_t2[ch+1];
      size_t pa = (size_t)(p0 + wm + mi*16 + r0);
      size_t pb = pa + 8;
      float x0 = fmaxf(fmaf(F.acc[mi][ni][0], s0, t0), 0.f);
      float x1 = fmaxf(fmaf(F.acc[mi][ni][1], s1, t1), 0.f);
      float y0 = fmaxf(fmaf(F.acc[mi][ni][2], s0, t0), 0.f);
      float y1 = fmaxf(fmaf(F.acc[mi][ni][3], s1, t1), 0.f);
      *(uint2*)(g_h2p + pa*CF + ch) = make_uint2(pack_split(x0), pack_split(x1));
      *(uint2*)(g_h2p + pb*CF + ch) = make_uint2(pack_split(y0), pack_split(y1));
    }
  }
}

// GEMM3: out = h2 @ w4^T + b4 -> encoded atomicMax cluster reduce
__global__ __launch_bounds__(256) void k_gemm3(const int* __restrict__ choice,
                                               const float* __restrict__ b4)
{
  extern __shared__ char smem[];
  __shared__ int scl[128];
  const int t = threadIdx.x, lane = t & 31, wid = t >> 5;
  const int p0 = blockIdx.x * 128, bb = blockIdx.x >> 6;
  const int ch0 = blockIdx.y * 128;

  for (int i=t; i<128; i+=256) scl[i] = choice[p0+i];
  __syncthreads();

  Frag F;
  gemm_core<false>(smem, scl, p0, bb, ch0, g_w4p, CF, F);

  const int wm = (wid & 1) * 64, wn = (wid >> 1) * 32;
  const int r0 = lane >> 2, cp = (lane & 3) * 2;
  #pragma unroll
  for (int mi=0;mi<4;mi++){
    int pa = wm + mi*16 + r0;
    unsigned* ra = &g_om[(size_t)(bb*NCLST + scl[pa])*CO];
    unsigned* rb = &g_om[(size_t)(bb*NCLST + scl[pa+8])*CO];
    #pragma unroll
    for (int ni=0;ni<4;ni++){
      int ch = ch0 + wn + ni*8 + cp;
      float b0 = b4[ch], b1 = b4[ch+1];
      atomicMax(&ra[ch],   enc(F.acc[mi][ni][0] + b0));
      atomicMax(&ra[ch+1], enc(F.acc[mi][ni][1] + b1));
      atomicMax(&rb[ch],   enc(F.acc[mi][ni][2] + b0));
      atomicMax(&rb[ch+1], enc(F.acc[mi][ni][3] + b1));
    }
  }
}

__global__ void k_final(float* __restrict__ out){
  int i = blockIdx.x*blockDim.x + threadIdx.x;
  if (i < BATCH*NCLST*CO) out[i] = dec(g_om[i]);
}

// =====================================================================
extern "C" void kernel_launch(void* const* d_in, const int* in_sizes, int n_in,
                              void* d_out, int out_size)
{
  const float* xyz    = (const float*)d_in[0];
  const int*   choice = (const int*)  d_in[1];
  const float* w1  = (const float*)d_in[2];
  const float* b1  = (const float*)d_in[3];
  const float* g1  = (const float*)d_in[4];
  const float* bb1 = (const float*)d_in[5];
  const float* m1  = (const float*)d_in[6];
  const float* v1  = (const float*)d_in[7];
  const float* w2  = (const float*)d_in[8];
  const float* b2  = (const float*)d_in[9];
  const float* w3  = (const float*)d_in[10];
  const float* b3  = (const float*)d_in[11];
  const float* g2  = (const float*)d_in[12];
  const float* bb2 = (const float*)d_in[13];
  const float* m2  = (const float*)d_in[14];
  const float* v2  = (const float*)d_in[15];
  const float* w4  = (const float*)d_in[16];
  const float* b4  = (const float*)d_in[17];

  size_t smem1 = (size_t)(TM1*C1 + 16*(C2+1)) * sizeof(float);
  size_t smemg = 4 * PLANE;   // 40 KB
  cudaFuncSetAttribute(k_stage1, cudaFuncAttributeMaxDynamicSharedMemorySize, (int)smem1);
  cudaFuncSetAttribute(k_gemm2,  cudaFuncAttributeMaxDynamicSharedMemorySize, (int)smemg);
  cudaFuncSetAttribute(k_gemm3,  cudaFuncAttributeMaxDynamicSharedMemorySize, (int)smemg);

  int ntot  = BATCH*NCLST*CO;
  int nprep = CF*CF + CO*CF + CF;

  k_init    <<<(ntot+255)/256, 256>>>();
  k_prep    <<<(nprep+255)/256, 256>>>(w3, w4, b3, g2, bb2, m2, v2);
  k_stage1  <<<PTOT/TM1, 256, smem1>>>(xyz, choice, w1,b1,g1,bb1,m1,v1,w2,b2);
  k_fg_split<<<(BATCH*NCLST*C2+255)/256, 256>>>();
  {
    dim3 g2d(PTOT/128, CF/128);   // 2048 x 4
    k_gemm2<<<g2d, 256, smemg>>>(choice);
    dim3 g3d(PTOT/128, CO/128);   // 2048 x 3
    k_gemm3<<<g3d, 256, smemg>>>(choice, b4);
  }
  k_final   <<<(ntot+255)/256, 256>>>((float*)d_out);
}

// round 4
// speedup vs baseline: 5.7019x; 1.3958x over previous
#include <cuda_runtime.h>
#include <cuda_bf16.h>
#include <stdint.h>

#define BATCH 32
#define NPTS  8192
#define NCLST 64
#define C1    128
#define C2    256
#define CF    512
#define CO    384
#define PTOT  (BATCH*NPTS)
#define ENC_NEG_INF 0x007FFFFFu

// smem plane geometry: rows of 32 bf16 (64B) + 16B pad -> cf-free ldmatrix
#define ROWB   80
#define PLANE  (128*ROWB)       // 10240 B
#define BUFB   (4*PLANE)        // 40960 B (Ah, Al, Bh, Bl)
#define KC     32

// ---------------- scratch (static device globals) ----------------
__device__ unsigned g_fg[BATCH*NCLST*C2];
__device__ unsigned g_om[BATCH*NCLST*CO];
__device__ __align__(16) uint16_t g_feat_h[(size_t)PTOT*C2];
__device__ __align__(16) uint16_t g_feat_l[(size_t)PTOT*C2];
__device__ __align__(16) uint16_t g_fg_h[BATCH*NCLST*C2];
__device__ __align__(16) uint16_t g_fg_l[BATCH*NCLST*C2];
__device__ __align__(16) uint16_t g_h2_h[(size_t)PTOT*CF];
__device__ __align__(16) uint16_t g_h2_l[(size_t)PTOT*CF];
__device__ __align__(16) uint16_t g_w2_h[C2*C1], g_w2_l[C2*C1];
__device__ __align__(16) uint16_t g_w3_h[CF*CF], g_w3_l[CF*CF];
__device__ __align__(16) uint16_t g_w4_h[CO*CF], g_w4_l[CO*CF];
__device__ float g_s2[CF], g_t2[CF];
__device__ __align__(16) float g_w1f[C1*4];     // folded layer1: wx,wy,wz,c

// ---------------- helpers ----------------
__device__ __forceinline__ unsigned enc(float f){
  unsigned u = __float_as_uint(f);
  return (u & 0x80000000u) ? ~u : (u | 0x80000000u);
}
__device__ __forceinline__ float dec(unsigned u){
  u = (u & 0x80000000u) ? (u & 0x7FFFFFFFu) : ~u;
  return __uint_as_float(u);
}
__device__ __forceinline__ void split2(float v, uint16_t& h, uint16_t& l){
  __nv_bfloat16 bh = __float2bfloat16(v);
  float r = v - __bfloat162float(bh);
  if (!(r == r)) r = 0.f;
  h = __bfloat16_as_ushort(bh);
  l = __bfloat16_as_ushort(__float2bfloat16(r));
}
__device__ __forceinline__ uint32_t smem_u32(const void* p){
  uint32_t a;
  asm("{ .reg .u64 t; cvta.to.shared.u64 t, %1; cvt.u32.u64 %0, t; }" : "=r"(a) : "l"(p));
  return a;
}
__device__ __forceinline__ void cp16(uint32_t dst, const void* src){
  asm volatile("cp.async.cg.shared.global [%0], [%1], 16;" :: "r"(dst), "l"(src));
}
#define CP_COMMIT() asm volatile("cp.async.commit_group;" ::: "memory")
#define CP_WAIT1()  asm volatile("cp.async.wait_group 1;"  ::: "memory")
#define CP_WAIT0()  asm volatile("cp.async.wait_group 0;"  ::: "memory")

__device__ __forceinline__ void ldsm4(uint32_t* r, uint32_t addr){
  asm volatile("ldmatrix.sync.aligned.m8n8.x4.shared.b16 {%0,%1,%2,%3}, [%4];"
    : "=r"(r[0]),"=r"(r[1]),"=r"(r[2]),"=r"(r[3]) : "r"(addr));
}
__device__ __forceinline__ void mma16816(float* c, const uint32_t* a, const uint32_t* b){
  asm volatile("mma.sync.aligned.m16n8k16.row.col.f32.bf16.bf16.f32 "
    "{%0,%1,%2,%3}, {%4,%5,%6,%7}, {%8,%9}, {%0,%1,%2,%3};"
    : "+f"(c[0]),"+f"(c[1]),"+f"(c[2]),"+f"(c[3])
    : "r"(a[0]),"r"(a[1]),"r"(a[2]),"r"(a[3]), "r"(b[0]),"r"(b[1]));
}

struct Frag { float acc[4][4][4]; };

// 3-term split-bf16 MMA over one staged 32-k buffer
__device__ __forceinline__ void mma_chunk(uint32_t sb, uint32_t aoff, uint32_t boff, Frag& F){
  const uint32_t aAh = sb, aAl = sb + PLANE, aBh = sb + 2*PLANE, aBl = sb + 3*PLANE;
  #pragma unroll
  for (int ks = 0; ks < 2; ks++){
    const uint32_t kb = ks * 32;
    uint32_t a[4][4], bH[2][4], bL[2][4];
    #pragma unroll
    for (int mi=0;mi<4;mi++) ldsm4(a[mi],  aAh + aoff + mi*(16*ROWB) + kb);
    #pragma unroll
    for (int nj=0;nj<2;nj++) ldsm4(bH[nj], aBh + boff + nj*(16*ROWB) + kb);
    #pragma unroll
    for (int mi=0;mi<4;mi++)
      #pragma unroll
      for (int nj=0;nj<2;nj++){
        mma16816(F.acc[mi][nj*2+0], a[mi], &bH[nj][0]);
        mma16816(F.acc[mi][nj*2+1], a[mi], &bH[nj][2]);
      }
    #pragma unroll
    for (int nj=0;nj<2;nj++) ldsm4(bL[nj], aBl + boff + nj*(16*ROWB) + kb);
    #pragma unroll
    for (int mi=0;mi<4;mi++)
      #pragma unroll
      for (int nj=0;nj<2;nj++){
        mma16816(F.acc[mi][nj*2+0], a[mi], &bL[nj][0]);
        mma16816(F.acc[mi][nj*2+1], a[mi], &bL[nj][2]);
      }
    #pragma unroll
    for (int mi=0;mi<4;mi++) ldsm4(a[mi], aAl + aoff + mi*(16*ROWB) + kb);
    #pragma unroll
    for (int mi=0;mi<4;mi++)
      #pragma unroll
      for (int nj=0;nj<2;nj++){
        mma16816(F.acc[mi][nj*2+0], a[mi], &bH[nj][0]);
        mma16816(F.acc[mi][nj*2+1], a[mi], &bH[nj][2]);
      }
  }
}

// =====================================================================
__global__ void k_init(){
  int i = blockIdx.x*blockDim.x + threadIdx.x;
  if (i < BATCH*NCLST*C2) g_fg[i] = ENC_NEG_INF;
  if (i < BATCH*NCLST*CO) g_om[i] = ENC_NEG_INF;
}

__global__ void k_prep(
    const float* __restrict__ w1, const float* __restrict__ b1,
    const float* __restrict__ bg1, const float* __restrict__ bb1,
    const float* __restrict__ bm1, const float* __restrict__ bv1,
    const float* __restrict__ w2,
    const float* __restrict__ w3, const float* __restrict__ w4,
    const float* __restrict__ b3,
    const float* __restrict__ bg2, const float* __restrict__ bb2,
    const float* __restrict__ bm2, const float* __restrict__ bv2)
{
  int i = blockIdx.x*blockDim.x + threadIdx.x;
  if (i < CF*CF){ uint16_t h,l; split2(w3[i],h,l); g_w3_h[i]=h; g_w3_l[i]=l; }
  int j = i - CF*CF;
  if (j >= 0 && j < CO*CF){ uint16_t h,l; split2(w4[j],h,l); g_w4_h[j]=h; g_w4_l[j]=l; }
  int k = i - CF*CF - CO*CF;
  if (k >= 0 && k < C2*C1){ uint16_t h,l; split2(w2[k],h,l); g_w2_h[k]=h; g_w2_l[k]=l; }
  int m = i - CF*CF - CO*CF - C2*C1;
  if (m >= 0 && m < CF){
    float s = bg2[m] * rsqrtf(bv2[m] + 1e-5f);
    g_s2[m] = s;
    g_t2[m] = bb2[m] + (b3[m] - bm2[m]) * s;
  }
  int q = i - CF*CF - CO*CF - C2*C1 - CF;
  if (q >= 0 && q < C1){
    float s = bg1[q] * rsqrtf(bv1[q] + 1e-5f);
    g_w1f[q*4+0] = w1[q*3+0]*s;
    g_w1f[q*4+1] = w1[q*3+1]*s;
    g_w1f[q*4+2] = w1[q*3+2]*s;
    g_w1f[q*4+3] = (b1[q] - bm1[q])*s + bb1[q];
  }
}

// =====================================================================
// Stage 1 (HMMA): feat = (relu(fold_bn1(xyz)))@w2^T + b2
// CTA = 128 pts x 128 ch, grid (2048, 2). A computed on the fly from xyz.
// =====================================================================
__global__ __launch_bounds__(256) void k_stage1(
    const float* __restrict__ xyz, const int* __restrict__ choice,
    const float* __restrict__ b2)
{
  extern __shared__ char smem[];
  __shared__ float sx[128][3];
  __shared__ int   scl[128];

  const int t = threadIdx.x, lane = t & 31, wid = t >> 5;
  const int p0 = blockIdx.x*128, bb = blockIdx.x >> 6;
  const int ch0 = blockIdx.y*128;

  for (int i=t; i<128*3; i+=256) sx[i/3][i%3] = xyz[(size_t)p0*3 + i];
  for (int i=t; i<128;   i+=256) scl[i] = choice[p0+i];
  __syncthreads();

  const uint32_t sb = smem_u32(smem);
  uint16_t* pAh = (uint16_t*)smem;
  uint16_t* pAl = (uint16_t*)(smem + PLANE);

  const int wm = (wid & 1)*64, wn = (wid >> 1)*32;
  const uint32_t aoff = (uint32_t)(wm + (lane & 15))*ROWB + ((lane >> 4) & 1)*16;
  const uint32_t boff = (uint32_t)(wn + (lane & 7) + ((lane >> 4) & 1)*8)*ROWB
                      + ((lane >> 3) & 1)*16;

  Frag F;
  #pragma unroll
  for (int mi=0;mi<4;mi++)
    #pragma unroll
    for (int ni=0;ni<4;ni++)
      #pragma unroll
      for (int c=0;c<4;c++) F.acc[mi][ni][c] = 0.f;

  for (int kc=0; kc<4; kc++){
    // B: w2 planes via cp.async
    for (int idx=t; idx<512; idx+=256){
      int row = idx >> 2, c = idx & 3;
      size_t off = (size_t)(ch0+row)*C1 + kc*KC + c*8;
      uint32_t so = (uint32_t)row*ROWB + c*16;
      cp16(sb + 2*PLANE + so, g_w2_h + off);
      cp16(sb + 3*PLANE + so, g_w2_l + off);
    }
    CP_COMMIT();
    // A: compute h = relu(fold(xyz)) on the fly, split to planes
    for (int idx=t; idx<4096; idx+=256){
      int row = idx >> 5, kp = idx & 31;
      int k = kc*KC + kp;
      float4 wf = *(const float4*)(g_w1f + 4*k);
      float h = fmaf(sx[row][0], wf.x, fmaf(sx[row][1], wf.y, fmaf(sx[row][2], wf.z, wf.w)));
      h = fmaxf(h, 0.f);
      uint16_t hh, hl; split2(h, hh, hl);
      uint32_t so = (uint32_t)row*(ROWB/2) + kp;   // uint16 index
      pAh[so] = hh; pAl[so] = hl;
    }
    CP_WAIT0();
    __syncthreads();
    mma_chunk(sb, aoff, boff, F);
    __syncthreads();
  }

  // epilogue: v = acc + b2 -> feat planes + cluster atomicMax
  const int r0 = lane >> 2, cp = (lane & 3)*2;
  #pragma unroll
  for (int mi=0;mi<4;mi++){
    int pa = wm + mi*16 + r0;
    size_t ga = (size_t)(p0 + pa), gb = ga + 8;
    unsigned* fra = &g_fg[(size_t)(bb*NCLST + scl[pa])*C2];
    unsigned* frb = &g_fg[(size_t)(bb*NCLST + scl[pa+8])*C2];
    #pragma unroll
    for (int ni=0;ni<4;ni++){
      int ch = ch0 + wn + ni*8 + cp;
      float b0 = b2[ch], b1v = b2[ch+1];
      float x0 = F.acc[mi][ni][0] + b0, x1 = F.acc[mi][ni][1] + b1v;
      float y0 = F.acc[mi][ni][2] + b0, y1 = F.acc[mi][ni][3] + b1v;
      uint16_t h0,l0,h1,l1;
      split2(x0,h0,l0); split2(x1,h1,l1);
      *(uint32_t*)(g_feat_h + ga*C2 + ch) = (uint32_t)h0 | ((uint32_t)h1<<16);
      *(uint32_t*)(g_feat_l + ga*C2 + ch) = (uint32_t)l0 | ((uint32_t)l1<<16);
      atomicMax(&fra[ch],   enc(x0));
      atomicMax(&fra[ch+1], enc(x1));
      split2(y0,h0,l0); split2(y1,h1,l1);
      *(uint32_t*)(g_feat_h + gb*C2 + ch) = (uint32_t)h0 | ((uint32_t)h1<<16);
      *(uint32_t*)(g_feat_l + gb*C2 + ch) = (uint32_t)l0 | ((uint32_t)l1<<16);
      atomicMax(&frb[ch],   enc(y0));
      atomicMax(&frb[ch+1], enc(y1));
    }
  }
}

__global__ void k_fg_split(){
  int i = blockIdx.x*blockDim.x + threadIdx.x;
  if (i < BATCH*NCLST*C2){
    uint16_t h,l; split2(dec(g_fg[i]), h, l);
    g_fg_h[i] = h; g_fg_l[i] = l;
  }
}

// =====================================================================
// Double-buffered cp.async HMMA core
// =====================================================================
template<bool GATHER_A>
__device__ __forceinline__ void gemm_core(
    uint32_t sb0, const int* scl, int p0, int bb, int ch0,
    const uint16_t* __restrict__ Ah, const uint16_t* __restrict__ Al,
    const uint16_t* __restrict__ Bh, const uint16_t* __restrict__ Bl,
    int KTOT, Frag& F)
{
  const int t = threadIdx.x, lane = t & 31, wid = t >> 5;
  const int wm = (wid & 1)*64, wn = (wid >> 1)*32;
  const uint32_t aoff = (uint32_t)(wm + (lane & 15))*ROWB + ((lane >> 4) & 1)*16;
  const uint32_t boff = (uint32_t)(wn + (lane & 7) + ((lane >> 4) & 1)*8)*ROWB
                      + ((lane >> 3) & 1)*16;

  #pragma unroll
  for (int mi=0;mi<4;mi++)
    #pragma unroll
    for (int ni=0;ni<4;ni++)
      #pragma unroll
      for (int c=0;c<4;c++) F.acc[mi][ni][c] = 0.f;

  const int NKC = KTOT / KC;

  #define ISSUE(kc) do { \
    uint32_t sbb = sb0 + ((kc)&1)*BUFB; \
    for (int idx=t; idx<512; idx+=256){ \
      int row = idx >> 2, c = idx & 3; \
      size_t off; \
      const uint16_t *sh, *sl; \
      if (GATHER_A && (kc) < 8){ \
        off = (size_t)(bb*NCLST + scl[row])*C2 + (kc)*KC + c*8; sh = g_fg_h; sl = g_fg_l; \
      } else if (GATHER_A){ \
        off = (size_t)(p0 + row)*C2 + ((kc)-8)*KC + c*8; sh = Ah; sl = Al; \
      } else { \
        off = (size_t)(p0 + row)*CF + (kc)*KC + c*8; sh = Ah; sl = Al; \
      } \
      uint32_t so = (uint32_t)row*ROWB + c*16; \
      cp16(sbb + so,         sh + off); \
      cp16(sbb + PLANE + so, sl + off); \
      size_t offb = (size_t)(ch0 + row)*CF + (kc)*KC + c*8; \
      cp16(sbb + 2*PLANE + so, Bh + offb); \
      cp16(sbb + 3*PLANE + so, Bl + offb); \
    } \
    CP_COMMIT(); \
  } while(0)

  ISSUE(0);
  for (int kc = 0; kc < NKC; kc++){
    if (kc + 1 < NKC){ ISSUE(kc+1); CP_WAIT1(); }
    else             { CP_WAIT0(); }
    __syncthreads();
    mma_chunk(sb0 + (kc&1)*BUFB, aoff, boff, F);
    __syncthreads();
  }
  #undef ISSUE
}

// GEMM2: h2 = relu(bn2(f @ w3^T + b3)) -> h2 planes
__global__ __launch_bounds__(256) void k_gemm2(const int* __restrict__ choice)
{
  extern __shared__ char smem[];
  __shared__ int scl[128];
  const int t = threadIdx.x, lane = t & 31, wid = t >> 5;
  const int p0 = blockIdx.x*128, bb = blockIdx.x >> 6;
  const int ch0 = blockIdx.y*128;

  for (int i=t; i<128; i+=256) scl[i] = choice[p0+i];
  __syncthreads();

  Frag F;
  gemm_core<true>(smem_u32(smem), scl, p0, bb, ch0, g_feat_h, g_feat_l, g_w3_h, g_w3_l, CF, F);

  const int wm = (wid & 1)*64, wn = (wid >> 1)*32;
  const int r0 = lane >> 2, cp = (lane & 3)*2;
  #pragma unroll
  for (int mi=0;mi<4;mi++){
    size_t pa = (size_t)(p0 + wm + mi*16 + r0), pb = pa + 8;
    #pragma unroll
    for (int ni=0;ni<4;ni++){
      int ch = ch0 + wn + ni*8 + cp;
      float s0 = g_s2[ch], s1 = g_s2[ch+1];
      float t0 = g_t2[ch], t1 = g_t2[ch+1];
      float x0 = fmaxf(fmaf(F.acc[mi][ni][0], s0, t0), 0.f);
      float x1 = fmaxf(fmaf(F.acc[mi][ni][1], s1, t1), 0.f);
      float y0 = fmaxf(fmaf(F.acc[mi][ni][2], s0, t0), 0.f);
      float y1 = fmaxf(fmaf(F.acc[mi][ni][3], s1, t1), 0.f);
      uint16_t h0,l0,h1,l1;
      split2(x0,h0,l0); split2(x1,h1,l1);
      *(uint32_t*)(g_h2_h + pa*CF + ch) = (uint32_t)h0 | ((uint32_t)h1<<16);
      *(uint32_t*)(g_h2_l + pa*CF + ch) = (uint32_t)l0 | ((uint32_t)l1<<16);
      split2(y0,h0,l0); split2(y1,h1,l1);
      *(uint32_t*)(g_h2_h + pb*CF + ch) = (uint32_t)h0 | ((uint32_t)h1<<16);
      *(uint32_t*)(g_h2_l + pb*CF + ch) = (uint32_t)l0 | ((uint32_t)l1<<16);
    }
  }
}

// GEMM3: out = h2 @ w4^T + b4 -> cluster atomicMax
__global__ __launch_bounds__(256) void k_gemm3(const int* __restrict__ choice,
                                               const float* __restrict__ b4)
{
  extern __shared__ char smem[];
  __shared__ int scl[128];
  const int t = threadIdx.x, lane = t & 31, wid = t >> 5;
  const int p0 = blockIdx.x*128, bb = blockIdx.x >> 6;
  const int ch0 = blockIdx.y*128;

  for (int i=t; i<128; i+=256) scl[i] = choice[p0+i];
  __syncthreads();

  Frag F;
  gemm_core<false>(smem_u32(smem), scl, p0, bb, ch0, g_h2_h, g_h2_l, g_w4_h, g_w4_l, CF, F);

  const int wm = (wid & 1)*64, wn = (wid >> 1)*32;
  const int r0 = lane >> 2, cp = (lane & 3)*2;
  #pragma unroll
  for (int mi=0;mi<4;mi++){
    int pa = wm + mi*16 + r0;
    unsigned* ra = &g_om[(size_t)(bb*NCLST + scl[pa])*CO];
    unsigned* rb = &g_om[(size_t)(bb*NCLST + scl[pa+8])*CO];
    #pragma unroll
    for (int ni=0;ni<4;ni++){
      int ch = ch0 + wn + ni*8 + cp;
      float b0 = b4[ch], b1 = b4[ch+1];
      atomicMax(&ra[ch],   enc(F.acc[mi][ni][0] + b0));
      atomicMax(&ra[ch+1], enc(F.acc[mi][ni][1] + b1));
      atomicMax(&rb[ch],   enc(F.acc[mi][ni][2] + b0));
      atomicMax(&rb[ch+1], enc(F.acc[mi][ni][3] + b1));
    }
  }
}

__global__ void k_final(float* __restrict__ out){
  int i = blockIdx.x*blockDim.x + threadIdx.x;
  if (i < BATCH*NCLST*CO) out[i] = dec(g_om[i]);
}

// =====================================================================
extern "C" void kernel_launch(void* const* d_in, const int* in_sizes, int n_in,
                              void* d_out, int out_size)
{
  const float* xyz    = (const float*)d_in[0];
  const int*   choice = (const int*)  d_in[1];
  const float* w1  = (const float*)d_in[2];
  const float* b1  = (const float*)d_in[3];
  const float* g1  = (const float*)d_in[4];
  const float* bb1 = (const float*)d_in[5];
  const float* m1  = (const float*)d_in[6];
  const float* v1  = (const float*)d_in[7];
  const float* w2  = (const float*)d_in[8];
  const float* b2  = (const float*)d_in[9];
  const float* w3  = (const float*)d_in[10];
  const float* b3  = (const float*)d_in[11];
  const float* g2  = (const float*)d_in[12];
  const float* bb2 = (const float*)d_in[13];
  const float* m2  = (const float*)d_in[14];
  const float* v2  = (const float*)d_in[15];
  const float* w4  = (const float*)d_in[16];
  const float* b4  = (const float*)d_in[17];

  size_t smem1 = BUFB;        // 40 KB (A + B planes, single buffer)
  size_t smemg = 2*BUFB;      // 80 KB (double buffer)
  cudaFuncSetAttribute(k_stage1, cudaFuncAttributeMaxDynamicSharedMemorySize, (int)smem1);
  cudaFuncSetAttribute(k_gemm2,  cudaFuncAttributeMaxDynamicSharedMemorySize, (int)smemg);
  cudaFuncSetAttribute(k_gemm3,  cudaFuncAttributeMaxDynamicSharedMemorySize, (int)smemg);

  int ntot  = BATCH*NCLST*CO;
  int nprep = CF*CF + CO*CF + C2*C1 + CF + C1;

  k_init    <<<(ntot+255)/256, 256>>>();
  k_prep    <<<(nprep+255)/256, 256>>>(w1,b1,g1,bb1,m1,v1,w2, w3,w4,b3,g2,bb2,m2,v2);
  {
    dim3 g1d(PTOT/128, C2/128);   // 2048 x 2
    k_stage1<<<g1d, 256, smem1>>>(xyz, choice, b2);
  }
  k_fg_split<<<(BATCH*NCLST*C2+255)/256, 256>>>();
  {
    dim3 g2d(PTOT/128, CF/128);   // 2048 x 4
    k_gemm2<<<g2d, 256, smemg>>>(choice);
    dim3 g3d(PTOT/128, CO/128);   // 2048 x 3
    k_gemm3<<<g3d, 256, smemg>>>(choice, b4);
  }
  k_final   <<<(ntot+255)/256, 256>>>((float*)d_out);
}